// round 2
// baseline (speedup 1.0000x reference)
#include <cuda_runtime.h>
#include <cstdint>

// Problem constants
#define BS      16
#define CIN     32
#define COUT    64
#define OUT_DIM 1024
#define DLEN    4096      // = OUT_DIM * 4
#define P_BLK   4         // patches per block
#define THREADS 256       // 64 o  x  4 pp
#define NBLOCKS (OUT_DIM / P_BLK)   // 256

// Shared x-tile layout: xs[c][kk][b], kk in [0,16), b in [0,16) floats,
// quad-of-b XOR-swizzled by (kk>>2) for conflict-free LDS.128.
// c-stride padded to 260 floats (260 % 32 == 4) to break producer-store phase alignment.
#define CSTRIDE 260
#define SMEM_FLOATS (CIN * CSTRIDE)   // 8320 floats = 33,280 B (< 48 KB static)

typedef unsigned long long ull;

__global__ __launch_bounds__(THREADS)
void lc1d_kernel(const float* __restrict__ x,
                 const float* __restrict__ w,
                 float* __restrict__ out)
{
    __shared__ float xs[SMEM_FLOATS];

    const int tid = threadIdx.x;
    const int blk = blockIdx.x;          // patch-block index: p0 = blk * P_BLK

    // ---------------- producer: stage x tile ----------------
    // x tile: x[b, c, d] for d in [p0*4, p0*4+16) -> 4 float4 per (b,c), 2048 float4 total.
    {
        const float4* x4 = reinterpret_cast<const float4*>(x);
        #pragma unroll
        for (int it = 0; it < 8; ++it) {
            int i = tid + it * THREADS;          // 0..2047
            int j = i & 3;                       // float4 within row (kk = 4j..4j+3)
            int c = (i >> 2) & 31;
            int b = i >> 7;                      // 0..15
            float4 v = x4[(size_t)(b * CIN + c) * (DLEN / 4) + (size_t)blk * P_BLK + j];
            // logical (b, kk) stored at quad slot ((b>>2) ^ j), preserving b&3 within quad
            int slot = ((b >> 2) ^ j) << 2;
            int base = c * CSTRIDE + (j * 4) * 16 + slot + (b & 3);
            xs[base          ] = v.x;
            xs[base + 16     ] = v.y;
            xs[base + 32     ] = v.z;
            xs[base + 48     ] = v.w;
        }
    }
    __syncthreads();

    // ---------------- consumer ----------------
    const int pp = tid & 3;        // local patch 0..3
    const int o  = tid >> 2;       // 0..63
    const int p  = blk * P_BLK + pp;

    // shared base address (u32) for ld.shared
    uint32_t sbase;
    asm("{ .reg .u64 t; cvta.to.shared.u64 t, %1; cvt.u32.u64 %0, t; }"
        : "=r"(sbase) : "l"(xs));

    // 8 packed f32x2 accumulators: acc[j] holds batches {2j, 2j+1}
    ull acc[8];
    #pragma unroll
    for (int q = 0; q < 8; ++q) acc[q] = 0ULL;

    const float4* w4 = reinterpret_cast<const float4*>(w);
    const size_t wbase = (size_t)o * CIN * (DLEN / 4) + (size_t)blk * P_BLK + pp;

    #pragma unroll 4
    for (int c = 0; c < CIN; ++c) {
        // w[o, c, 4p .. 4p+3] : one perfectly contiguous float4
        float4 wv = __ldg(&w4[wbase + (size_t)c * (DLEN / 4)]);
        ull wp0, wp1, wp2, wp3;    // {w,w} duplicated into both f32x2 lanes
        asm("mov.b64 %0, {%1, %1};" : "=l"(wp0) : "f"(wv.x));
        asm("mov.b64 %0, {%1, %1};" : "=l"(wp1) : "f"(wv.y));
        asm("mov.b64 %0, {%1, %1};" : "=l"(wp2) : "f"(wv.z));
        asm("mov.b64 %0, {%1, %1};" : "=l"(wp3) : "f"(wv.w));
        const ull wk[4] = {wp0, wp1, wp2, wp3};

        #pragma unroll
        for (int k = 0; k < 4; ++k) {
            const uint32_t row = sbase + 4u * (uint32_t)(c * CSTRIDE + (pp * 4 + k) * 16);
            #pragma unroll
            for (int q = 0; q < 4; ++q) {
                // swizzled slot: physical quad (q ^ pp) holds logical batch-quad q
                uint32_t a = row + (uint32_t)(((q ^ pp) << 2) * 4);
                ull v0, v1;
                asm("ld.shared.v2.u64 {%0, %1}, [%2];"
                    : "=l"(v0), "=l"(v1) : "r"(a));
                asm("fma.rn.f32x2 %0, %1, %2, %0;"
                    : "+l"(acc[2 * q    ]) : "l"(v0), "l"(wk[k]));
                asm("fma.rn.f32x2 %0, %1, %2, %0;"
                    : "+l"(acc[2 * q + 1]) : "l"(v1), "l"(wk[k]));
            }
        }
    }

    // ---------------- epilogue: scale by 1/sqrt(32) and store ----------------
    ull sc;
    asm("mov.b64 %0, {%1, %1};" : "=l"(sc) : "f"(0.17677669529663687f));

    #pragma unroll
    for (int j = 0; j < 8; ++j) {
        ull r;
        asm("mul.rn.f32x2 %0, %1, %2;" : "=l"(r) : "l"(acc[j]), "l"(sc));
        float lo, hi;
        asm("mov.b64 {%0, %1}, %2;" : "=f"(lo), "=f"(hi) : "l"(r));
        int b0 = 2 * j;
        out[((b0       * COUT + o) << 10) + p] = lo;
        out[(((b0 + 1) * COUT + o) << 10) + p] = hi;
    }
}

extern "C" void kernel_launch(void* const* d_in, const int* in_sizes, int n_in,
                              void* d_out, int out_size)
{
    const float* x = (const float*)d_in[0];   // [16, 32, 4096]
    const float* w = (const float*)d_in[1];   // [64, 32, 4096]
    float* out = (float*)d_out;               // [16, 64, 1024]
    (void)in_sizes; (void)n_in; (void)out_size;

    lc1d_kernel<<<NBLOCKS, THREADS>>>(x, w, out);
}

// round 3
// speedup vs baseline: 1.8506x; 1.8506x over previous
#include <cuda_runtime.h>
#include <cstdint>

#define BS      16
#define CIN     32
#define COUT    64
#define OUT_DIM 1024
#define P_BLK   4
#define THREADS 128            // 8 og x 4 bg x 4 pp
#define NBLOCKS (OUT_DIM / P_BLK)   // 256

// smem x tile: per c a 256-float region [pp:4][b:16][k:4], granule (16B) = one
// batch's k-quad. Granule index G = pp*16 + b, stored at phys = G ^ pp
// (swizzle => conflict-free consumer LDS.128). c-stride padded to 260 floats.
#define CSTRIDE 260
#define SMEM_FLOATS (CIN * CSTRIDE)   // 8320 floats = 33,280 B

typedef unsigned long long ull;

__global__ __launch_bounds__(THREADS)
void lc1d_v2(const float* __restrict__ x,
             const float* __restrict__ w,
             float* __restrict__ out)
{
    __shared__ __align__(16) float xs[SMEM_FLOATS];

    const int tid = threadIdx.x;
    const int blk = blockIdx.x;

    // ---------------- producer: stage x tile (16 float4 per thread) ----------
    {
        const float4* x4 = reinterpret_cast<const float4*>(x);
        #pragma unroll
        for (int it = 0; it < 16; ++it) {
            int i = it * THREADS + tid;          // 0..2047
            int j = i & 3;                       // patch-within-block (pp of data)
            int c = (i >> 2) & 31;
            int b = i >> 7;                      // 0..15
            float4 v = x4[(size_t)(b * CIN + c) * (OUT_DIM) + (size_t)blk * P_BLK + j];
            int g = 16 * j + (b ^ j);            // swizzled granule
            *reinterpret_cast<float4*>(&xs[c * CSTRIDE + 4 * g]) = v;
        }
    }
    __syncthreads();

    // ---------------- consumer ----------------
    const int pp = tid & 3;
    const int bg = (tid >> 2) & 3;     // batch group: batches 4*bg..4*bg+3
    const int og = tid >> 4;           // o group: o = 8*og + i
    const int p  = blk * P_BLK + pp;

    uint32_t sbase;
    asm("{ .reg .u64 t; cvta.to.shared.u64 t, %1; cvt.u32.u64 %0, t; }"
        : "=r"(sbase) : "l"(xs));

    // 4 shared addresses (one per owned batch), swizzled; advance by c-stride.
    uint32_t a0, a1, a2, a3;
    {
        int G0 = pp * 16 + 4 * bg;
        a0 = sbase + 16u * (uint32_t)((G0 + 0) ^ pp);
        a1 = sbase + 16u * (uint32_t)((G0 + 1) ^ pp);
        a2 = sbase + 16u * (uint32_t)((G0 + 2) ^ pp);
        a3 = sbase + 16u * (uint32_t)((G0 + 3) ^ pp);
    }

    // acc[i][q]: k-even/k-odd partial sums packed in f32x2 lanes
    ull acc[32];
    #pragma unroll
    for (int t = 0; t < 32; ++t) acc[t] = 0ULL;

    // w as ulonglong2: index = o*32768 + c*1024 + blk*4 + pp
    const ulonglong2* wp = reinterpret_cast<const ulonglong2*>(w)
                         + (size_t)og * 8 * 32768 + (size_t)blk * P_BLK + pp;

    // double-buffered w tiles: 8 o's x {lo=(k0,k1), hi=(k2,k3)}
    ull wlo[2][8], whi[2][8];
    #pragma unroll
    for (int i = 0; i < 8; ++i) {
        ulonglong2 t = wp[(size_t)i * 32768];
        wlo[0][i] = t.x; whi[0][i] = t.y;
    }

    #pragma unroll 2
    for (int c = 0; c < CIN; ++c) {
        const int cur = c & 1, nxt = cur ^ 1;
        if (c + 1 < CIN) {
            const ulonglong2* wn = wp + (size_t)(c + 1) * 1024;
            #pragma unroll
            for (int i = 0; i < 8; ++i) {
                ulonglong2 t = wn[(size_t)i * 32768];
                wlo[nxt][i] = t.x; whi[nxt][i] = t.y;
            }
        }

        // x for 4 owned batches: {k0,k1} and {k2,k3} packed u64s
        ull xlo[4], xhi[4];
        asm("ld.shared.v2.u64 {%0, %1}, [%2];" : "=l"(xlo[0]), "=l"(xhi[0]) : "r"(a0));
        asm("ld.shared.v2.u64 {%0, %1}, [%2];" : "=l"(xlo[1]), "=l"(xhi[1]) : "r"(a1));
        asm("ld.shared.v2.u64 {%0, %1}, [%2];" : "=l"(xlo[2]), "=l"(xhi[2]) : "r"(a2));
        asm("ld.shared.v2.u64 {%0, %1}, [%2];" : "=l"(xlo[3]), "=l"(xhi[3]) : "r"(a3));
        a0 += CSTRIDE * 4; a1 += CSTRIDE * 4; a2 += CSTRIDE * 4; a3 += CSTRIDE * 4;

        #pragma unroll
        for (int i = 0; i < 8; ++i) {
            const ull wl = wlo[cur][i], wh = whi[cur][i];
            #pragma unroll
            for (int q = 0; q < 4; ++q) {
                asm("fma.rn.f32x2 %0, %1, %2, %0;"
                    : "+l"(acc[i * 4 + q]) : "l"(xlo[q]), "l"(wl));
                asm("fma.rn.f32x2 %0, %1, %2, %0;"
                    : "+l"(acc[i * 4 + q]) : "l"(xhi[q]), "l"(wh));
            }
        }
    }

    // ---------------- epilogue: fold lanes, scale, store ----------------
    const float sc = 0.17677669529663687f;   // 1/sqrt(32)
    #pragma unroll
    for (int i = 0; i < 8; ++i) {
        const int o = og * 8 + i;
        #pragma unroll
        for (int q = 0; q < 4; ++q) {
            float lo, hi;
            asm("mov.b64 {%0, %1}, %2;" : "=f"(lo), "=f"(hi) : "l"(acc[i * 4 + q]));
            const int b = bg * 4 + q;
            out[(size_t)b * (COUT * OUT_DIM) + (size_t)o * OUT_DIM + p] = (lo + hi) * sc;
        }
    }
}

extern "C" void kernel_launch(void* const* d_in, const int* in_sizes, int n_in,
                              void* d_out, int out_size)
{
    const float* x = (const float*)d_in[0];   // [16, 32, 4096]
    const float* w = (const float*)d_in[1];   // [64, 32, 4096]
    float* out = (float*)d_out;               // [16, 64, 1024]
    (void)in_sizes; (void)n_in; (void)out_size;

    lc1d_v2<<<NBLOCKS, THREADS>>>(x, w, out);
}